// round 13
// baseline (speedup 1.0000x reference)
#include <cuda_runtime.h>
#include <cuda_bf16.h>

// GateSparsemaxK: per-row sparsemax gate, B=8192 rows x R=4096 cols, fp32.
// z = where(mask>0.5, s, -1e9) / 0.7 ; p = sparsemax_row(z) ; out = min(k*p, 1)
//
// Sort-free sparsemax (Michelot fixed point): tau* >= max(z)-1, iterate
//   tau <- (sum_{z>tau} z - 1)/count_{z>tau} until support stabilizes.
//
// R13: DUAL-ROW CTA. Each CTA loads TWO rows into registers back-to-back,
//      then runs both rows' max + Michelot FUSED (one barrier sequence
//      reduces both rows; halves barriers/row), then stores both.
//      Mechanism: in-kernel DRAM is only ~77% busy — idle during each CTA's
//      compute window. Row1's demand loads (same CTA, register-resident, no
//      eviction/duplication unlike R10's failed prefetch) fill that window.

constexpr int R_DIM   = 4096;
constexpr int THREADS = 128;
constexpr int WARPS   = THREADS / 32;         // 4
constexpr int PER     = R_DIM / THREADS;      // 32 floats per thread per row
constexpr int NV      = PER / 4;              // 8 float4 per thread per row

__global__ void __launch_bounds__(THREADS)
gate_sparsemax_kernel(const float* __restrict__ S,
                      const float* __restrict__ M,
                      const unsigned int* __restrict__ kraw,
                      float* __restrict__ O)
{
    const int t = threadIdx.x;
    const size_t base0 = (size_t)(2 * blockIdx.x)     * R_DIM;
    const size_t base1 = (size_t)(2 * blockIdx.x + 1) * R_DIM;

    const float4* s40 = reinterpret_cast<const float4*>(S + base0);
    const float4* m40 = reinterpret_cast<const float4*>(M + base0);
    const float4* s41 = reinterpret_cast<const float4*>(S + base1);
    const float4* m41 = reinterpret_cast<const float4*>(M + base1);
    float4*       o40 = reinterpret_cast<float4*>(O + base0);
    float4*       o41 = reinterpret_cast<float4*>(O + base1);

    __shared__ float sh0s[WARPS], sh0c[WARPS];
    __shared__ float sh1s[WARPS], sh1c[WARPS];
    __shared__ float bcast[4];   // tau0, cnt0, tau1, cnt1

    const float TAU_INV = 1.0f / 0.7f;
    const float NEGZ    = -1.0e9f * TAU_INV;

    // ---- read pass: row0 then row1, all into registers ----
    float z0[PER], z1[PER];
    float lmax0 = -3.0e9f, lmax1 = -3.0e9f;
#pragma unroll
    for (int i = 0; i < NV; i++) {
        float4 sv = s40[t + i * THREADS];
        float4 mv = m40[t + i * THREADS];
        float* zp = &z0[i * 4];
        zp[0] = (mv.x > 0.5f) ? sv.x * TAU_INV : NEGZ;
        zp[1] = (mv.y > 0.5f) ? sv.y * TAU_INV : NEGZ;
        zp[2] = (mv.z > 0.5f) ? sv.z * TAU_INV : NEGZ;
        zp[3] = (mv.w > 0.5f) ? sv.w * TAU_INV : NEGZ;
        lmax0 = fmaxf(lmax0, fmaxf(fmaxf(zp[0], zp[1]), fmaxf(zp[2], zp[3])));
    }
#pragma unroll
    for (int i = 0; i < NV; i++) {
        float4 sv = s41[t + i * THREADS];
        float4 mv = m41[t + i * THREADS];
        float* zp = &z1[i * 4];
        zp[0] = (mv.x > 0.5f) ? sv.x * TAU_INV : NEGZ;
        zp[1] = (mv.y > 0.5f) ? sv.y * TAU_INV : NEGZ;
        zp[2] = (mv.z > 0.5f) ? sv.z * TAU_INV : NEGZ;
        zp[3] = (mv.w > 0.5f) ? sv.w * TAU_INV : NEGZ;
        lmax1 = fmaxf(lmax1, fmaxf(fmaxf(zp[0], zp[1]), fmaxf(zp[2], zp[3])));
    }

    // ---- fused block max for both rows ----
#pragma unroll
    for (int o = 16; o; o >>= 1) {
        lmax0 = fmaxf(lmax0, __shfl_xor_sync(0xffffffffu, lmax0, o));
        lmax1 = fmaxf(lmax1, __shfl_xor_sync(0xffffffffu, lmax1, o));
    }
    if ((t & 31) == 0) { sh0s[t >> 5] = lmax0; sh1s[t >> 5] = lmax1; }
    __syncthreads();
    if (t < 32) {
        float v0 = (t < WARPS) ? sh0s[t] : -3.0e9f;
        float v1 = (t < WARPS) ? sh1s[t] : -3.0e9f;
#pragma unroll
        for (int o = 2; o; o >>= 1) {
            v0 = fmaxf(v0, __shfl_xor_sync(0xffffffffu, v0, o));
            v1 = fmaxf(v1, __shfl_xor_sync(0xffffffffu, v1, o));
        }
        if (t == 0) { bcast[0] = v0; bcast[2] = v1; }
    }
    __syncthreads();

    float tau0 = bcast[0] - 1.0f;
    float tau1 = bcast[2] - 1.0f;

    // ---- fused Michelot for both rows ----
    float cprev0 = -1.0f, cprev1 = -1.0f;
    bool done0 = false, done1 = false;
    for (int iter = 0; iter < 64 && !(done0 && done1); iter++) {
        float ls0 = 0.0f, lc0 = 0.0f, ls1 = 0.0f, lc1 = 0.0f;
#pragma unroll
        for (int i = 0; i < PER; i++) {
            if (z0[i] > tau0) { ls0 += z0[i]; lc0 += 1.0f; }
            if (z1[i] > tau1) { ls1 += z1[i]; lc1 += 1.0f; }
        }
#pragma unroll
        for (int o = 16; o; o >>= 1) {
            ls0 += __shfl_xor_sync(0xffffffffu, ls0, o);
            lc0 += __shfl_xor_sync(0xffffffffu, lc0, o);
            ls1 += __shfl_xor_sync(0xffffffffu, ls1, o);
            lc1 += __shfl_xor_sync(0xffffffffu, lc1, o);
        }
        if ((t & 31) == 0) {
            sh0s[t >> 5] = ls0; sh0c[t >> 5] = lc0;
            sh1s[t >> 5] = ls1; sh1c[t >> 5] = lc1;
        }
        __syncthreads();
        if (t < 32) {
            float vs0 = (t < WARPS) ? sh0s[t] : 0.0f;
            float vc0 = (t < WARPS) ? sh0c[t] : 0.0f;
            float vs1 = (t < WARPS) ? sh1s[t] : 0.0f;
            float vc1 = (t < WARPS) ? sh1c[t] : 0.0f;
#pragma unroll
            for (int o = 2; o; o >>= 1) {
                vs0 += __shfl_xor_sync(0xffffffffu, vs0, o);
                vc0 += __shfl_xor_sync(0xffffffffu, vc0, o);
                vs1 += __shfl_xor_sync(0xffffffffu, vs1, o);
                vc1 += __shfl_xor_sync(0xffffffffu, vc1, o);
            }
            if (t == 0) {
                bcast[0] = (vc0 > 0.5f) ? (vs0 - 1.0f) / vc0 : 0.0f;
                bcast[1] = vc0;
                bcast[2] = (vc1 > 0.5f) ? (vs1 - 1.0f) / vc1 : 0.0f;
                bcast[3] = vc1;
            }
        }
        __syncthreads();
        float cnt0 = bcast[1], cnt1 = bcast[3];
        if (!done0) {
            if (cnt0 < 0.5f) done0 = true;            // degenerate guard
            else {
                tau0 = bcast[0];
                if (cnt0 == cprev0) done0 = true;     // fixed point
                cprev0 = cnt0;
            }
        }
        if (!done1) {
            if (cnt1 < 0.5f) done1 = true;
            else {
                tau1 = bcast[2];
                if (cnt1 == cprev1) done1 = true;
                cprev1 = cnt1;
            }
        }
        __syncthreads();                               // protect sh_* reuse
    }

    // ---- budget scalar k: robust to int32 or float32 encoding ----
    unsigned int kb = *kraw;
    float kf = (kb < (1u << 23)) ? (float)(int)kb : __uint_as_float(kb);

    // ---- write pass: both rows ----
#pragma unroll
    for (int i = 0; i < NV; i++) {
        float* zp = &z0[i * 4];
        float4 ov;
        ov.x = fminf(kf * fmaxf(zp[0] - tau0, 0.0f), 1.0f);
        ov.y = fminf(kf * fmaxf(zp[1] - tau0, 0.0f), 1.0f);
        ov.z = fminf(kf * fmaxf(zp[2] - tau0, 0.0f), 1.0f);
        ov.w = fminf(kf * fmaxf(zp[3] - tau0, 0.0f), 1.0f);
        o40[t + i * THREADS] = ov;
    }
#pragma unroll
    for (int i = 0; i < NV; i++) {
        float* zp = &z1[i * 4];
        float4 ov;
        ov.x = fminf(kf * fmaxf(zp[0] - tau1, 0.0f), 1.0f);
        ov.y = fminf(kf * fmaxf(zp[1] - tau1, 0.0f), 1.0f);
        ov.z = fminf(kf * fmaxf(zp[2] - tau1, 0.0f), 1.0f);
        ov.w = fminf(kf * fmaxf(zp[3] - tau1, 0.0f), 1.0f);
        o41[t + i * THREADS] = ov;
    }
}

extern "C" void kernel_launch(void* const* d_in, const int* in_sizes, int n_in,
                              void* d_out, int out_size)
{
    const float* s = (const float*)d_in[0];
    const float* m = (const float*)d_in[1];
    const unsigned int* k = (const unsigned int*)d_in[2];
    float* out = (float*)d_out;

    int B = in_sizes[0] / R_DIM;
    if (B <= 0) B = out_size / R_DIM;    // defensive fallback
    gate_sparsemax_kernel<<<B / 2, THREADS>>>(s, m, k, out);
}